// round 5
// baseline (speedup 1.0000x reference)
#include <cuda_runtime.h>
#include <math.h>

// ---------------------------------------------------------------------------
// SoftLabelLoss: loss = max( (1/B) * sum_i [ e[t_i] - dot(soft[t_i], x_i) + lse(x_i) ], 0 )
//   soft[t][c] = 0.8*(c==t) + 0.2*sim[t][c]/rowsum(sim[t]);  e[t] = sum soft*log(soft)
// TMA-staged single pass: cp.async.bulk rings 32-row logit tiles through smem
// (5-deep), warp-per-row compute from smem, fixed-point atomic finalize.
// ---------------------------------------------------------------------------

#define FXSCALE 4294967296.0   // 2^32

__device__ unsigned long long g_sum  = 0ULL;
__device__ unsigned int       g_done = 0u;

// --- PTX helpers ---------------------------------------------------------------
__device__ __forceinline__ unsigned smem_u32(const void* p) {
    unsigned r;
    asm("{ .reg .u64 t; cvta.to.shared.u64 t, %1; cvt.u32.u64 %0, t; }"
        : "=r"(r) : "l"(p));
    return r;
}
#define MBAR_INIT(a, c) \
    asm volatile("mbarrier.init.shared.b64 [%0], %1;" :: "r"(a), "r"(c) : "memory")
#define MBAR_EXPECT(a, bytes) \
    asm volatile("mbarrier.arrive.expect_tx.shared.b64 _, [%0], %1;" :: "r"(a), "r"(bytes) : "memory")
#define TMA_BULK_G2S(dst, src, bytes, mbar) \
    asm volatile("cp.async.bulk.shared::cluster.global.mbarrier::complete_tx::bytes [%0], [%1], %2, [%3];" \
                 :: "r"(dst), "l"(src), "r"(bytes), "r"(mbar) : "memory")

__device__ __forceinline__ void mbar_wait(unsigned addr, unsigned phase) {
    asm volatile(
        "{\n\t"
        ".reg .pred P;\n\t"
        "W_%=:\n\t"
        "mbarrier.try_wait.parity.acquire.cta.shared::cta.b64 P, [%0], %1, 0x989680;\n\t"
        "@P bra D_%=;\n\t"
        "bra W_%=;\n\t"
        "D_%=:\n\t"
        "}" :: "r"(addr), "r"(phase) : "memory");
}

// --- cooperative in-block table build (any C) -----------------------------------
__device__ __forceinline__ void build_table(const float* __restrict__ sim,
                                            float* s_soft, float* s_ent,
                                            int C, int lane, int warp) {
    for (int t = warp; t < C; t += 32) {
        const float* srow = sim + (size_t)t * C;
        float s = 0.0f;
        for (int c = lane; c < C; c += 32) {
            float v = __ldg(srow + c);
            s_soft[t * C + c] = v;
            s += v;
        }
        #pragma unroll
        for (int o = 16; o; o >>= 1) s += __shfl_xor_sync(0xffffffffu, s, o);
        float inv = 0.2f / s;                 // smoothing folded in
        float p = 0.0f;
        for (int c = lane; c < C; c += 32) {
            float soft = s_soft[t * C + c] * inv + (c == t ? 0.8f : 0.0f);
            s_soft[t * C + c] = soft;
            p += (soft > 0.0f) ? soft * __logf(soft) : 0.0f;
        }
        #pragma unroll
        for (int o = 16; o; o >>= 1) p += __shfl_xor_sync(0xffffffffu, p, o);
        if (lane == 0) s_ent[t] = p;
    }
}

// --- deterministic fixed-point finalize -------------------------------------------
__device__ __forceinline__ void block_finalize(float acc, int lane, int warp,
                                               double* s_w, float* out, int B) {
    double d = (double)acc;
    #pragma unroll
    for (int o = 16; o; o >>= 1) d += __shfl_xor_sync(0xffffffffu, d, o);
    if (lane == 0) s_w[warp] = d;
    __syncthreads();
    if (warp == 0) {
        int nw = (blockDim.x + 31) >> 5;
        double v = (lane < nw) ? s_w[lane] : 0.0;
        #pragma unroll
        for (int o = 16; o; o >>= 1) v += __shfl_xor_sync(0xffffffffu, v, o);
        if (lane == 0) {
            long long q = __double2ll_rn(v * FXSCALE);
            atomicAdd(&g_sum, (unsigned long long)q);
            __threadfence();
            unsigned int tk = atomicAdd(&g_done, 1u);
            if (tk == gridDim.x - 1) {
                unsigned long long raw = atomicAdd(&g_sum, 0ULL);
                double loss = ((double)(long long)raw / FXSCALE) / (double)B;
                out[0] = (float)(loss > 0.0 ? loss : 0.0);
                g_sum  = 0ULL;
                g_done = 0u;
                __threadfence();
            }
        }
    }
}

// --- TMA-staged main kernel (C compile-time) ----------------------------------------
template<int C>
__global__ __launch_bounds__(1024, 1)
void slloss_tma(const float* __restrict__ logits,
                const int*   __restrict__ targets,
                const float* __restrict__ sim,
                float* __restrict__ out, int B) {
    constexpr int C2    = C / 2;
    constexpr int ITER  = (C2 + 31) / 32;
    constexpr int TROWS = 32;
    constexpr int NBUF  = 5;
    constexpr unsigned ROWB  = C * 4;
    constexpr unsigned TILEB = TROWS * ROWB;

    extern __shared__ __align__(16) unsigned char smraw[];
    unsigned long long* s_mbar = (unsigned long long*)smraw;            // NBUF mbars (<=64B)
    double* s_w    = (double*)(smraw + 64);                             // 32 doubles
    float*  s_soft = (float*)(smraw + 64 + 256);                        // C*C
    float*  s_ent  = s_soft + C * C;                                    // C
    constexpr int OFF_TILE = ((64 + 256 + C * C * 4 + C * 4) + 15) & ~15;
    float*  s_tile = (float*)(smraw + OFF_TILE);                        // NBUF * TROWS * C

    const int tid  = threadIdx.x;
    const int lane = tid & 31;
    const int warp = tid >> 5;
    const unsigned mbar_b = smem_u32(s_mbar);
    const unsigned tile_b = smem_u32(s_tile);

    long long ntiles = ((long long)B + TROWS - 1) / TROWS;
    long long per = (ntiles + gridDim.x - 1) / gridDim.x;
    long long t0 = (long long)blockIdx.x * per;
    long long t1 = t0 + per; if (t1 > ntiles) t1 = ntiles;
    if (t0 > t1) t0 = t1;
    const int n = (int)(t1 - t0);

    if (tid == 0) {
        #pragma unroll
        for (int i = 0; i < NBUF; i++) MBAR_INIT(mbar_b + 8u * i, 1);
    }
    __syncthreads();

    // prologue: fill the ring (skip partial tail tiles — those read gmem directly)
    if (tid == 0) {
        int pre = n < NBUF ? n : NBUF;
        for (int i = 0; i < pre; i++) {
            long long R0 = (t0 + i) * TROWS;
            if (R0 + TROWS <= (long long)B) {
                MBAR_EXPECT(mbar_b + 8u * i, TILEB);
                TMA_BULK_G2S(tile_b + (unsigned)i * TILEB, logits + R0 * C, TILEB, mbar_b + 8u * i);
            }
        }
    }

    build_table(sim, s_soft, s_ent, C, lane, warp);   // overlaps with TMA fills
    __syncthreads();

    float acc = 0.0f;

    for (int i = 0; i < n; i++) {
        const int      p  = i - (i / NBUF) * NBUF;
        const unsigned ph = (unsigned)((i / NBUF) & 1);
        const long long R0 = (t0 + i) * TROWS;
        const bool fullt = (R0 + TROWS <= (long long)B);

        if (fullt) mbar_wait(mbar_b + 8u * p, ph);

        long long gr = R0 + warp;
        int  t     = (gr < B) ? __ldg(targets + gr) : -1;
        bool valid = (t >= 0) && (gr < B);
        int  tw    = (t >= 0) ? t : 0;

        const float2* wv = (const float2*)(s_soft + tw * C);
        const float2* xv = fullt
            ? (const float2*)(s_tile + (size_t)p * (TROWS * C) + warp * C)
            : (gr < B ? (const float2*)(logits + gr * (long long)C)
                      : (const float2*)s_tile);

        float se = 0.0f, dt = 0.0f;
        #pragma unroll
        for (int k = 0; k < ITER; k++) {
            int j = lane + 32 * k;
            if ((C2 % 32 == 0) || j < C2) {
                float2 x = xv[j];
                float2 w = wv[j];
                se += __expf(x.x) + __expf(x.y);
                dt = fmaf(w.x, x.x, dt);
                dt = fmaf(w.y, x.y, dt);
            }
        }
        #pragma unroll
        for (int o = 16; o; o >>= 1) se += __shfl_xor_sync(0xffffffffu, se, o);

        if (valid) {
            acc -= dt;                                   // dot stays lane-private
            if (lane == 0) acc += s_ent[t] + __logf(se);
        }

        __syncthreads();                                 // everyone done with buf p

        const int nx = i + NBUF;
        if (tid == 0 && nx < n) {
            long long R2 = (t0 + nx) * TROWS;
            if (R2 + TROWS <= (long long)B) {
                MBAR_EXPECT(mbar_b + 8u * p, TILEB);
                TMA_BULK_G2S(tile_b + (unsigned)p * TILEB, logits + R2 * C, TILEB, mbar_b + 8u * p);
            }
        }
    }

    block_finalize(acc, lane, warp, s_w, out, B);
}

// --- generic fallback (any C) ---------------------------------------------------------
__global__ __launch_bounds__(1024, 1)
void slloss_fused_gen(const float* __restrict__ logits,
                      const int*   __restrict__ targets,
                      const float* __restrict__ sim,
                      float* __restrict__ out,
                      int B, int C) {
    extern __shared__ float smemf[];
    float*  s_soft = smemf;
    float*  s_ent  = smemf + C * C;
    double* s_w    = (double*)(smemf + C * C + ((C + 1) & ~1));

    const int tid = threadIdx.x, lane = tid & 31, warp = tid >> 5;
    build_table(sim, s_soft, s_ent, C, lane, warp);
    __syncthreads();

    const int NW = gridDim.x * 32;
    const int gw = blockIdx.x * 32 + warp;
    long long per = ((long long)B + NW - 1) / NW;
    long long r0 = (long long)gw * per; if (r0 > B) r0 = B;
    long long r1 = r0 + per;            if (r1 > B) r1 = B;

    float acc = 0.0f;
    for (long long row = r0; row < r1; row++) {
        int t = __ldg(&targets[row]);
        if (t < 0) continue;
        const float* lg = logits + (size_t)row * C;
        const float* sw = s_soft + t * C;
        float se = 0.f, dt = 0.f;
        for (int c = lane; c < C; c += 32) {
            float x = __ldg(lg + c);
            se += __expf(x);
            dt = fmaf(sw[c], x, dt);
        }
        #pragma unroll
        for (int o = 16; o; o >>= 1) se += __shfl_xor_sync(0xffffffffu, se, o);
        acc -= dt;
        if (lane == 0) acc += s_ent[t] + __logf(se);
    }
    block_finalize(acc, lane, warp, s_w, out, B);
}

extern "C" void kernel_launch(void* const* d_in, const int* in_sizes, int n_in,
                              void* d_out, int out_size) {
    const float* logits  = (const float*)d_in[0];
    const int*   targets = (const int*)  d_in[1];
    const float* sim     = (const float*)d_in[2];
    float*       out     = (float*)d_out;

    int B = in_sizes[1];
    int C = in_sizes[0] / B;

    int nsm = 148;
    cudaDeviceGetAttribute(&nsm, cudaDevAttrMultiProcessorCount, 0);

    if (C == 170) {
        constexpr int Cc = 170, TROWS = 32, NBUF = 5;
        size_t off_tile = ((64 + 256 + (size_t)Cc * Cc * 4 + Cc * 4) + 15) & ~(size_t)15;
        size_t smem = off_tile + (size_t)NBUF * TROWS * Cc * 4;
        cudaFuncSetAttribute(slloss_tma<Cc>, cudaFuncAttributeMaxDynamicSharedMemorySize, (int)smem);
        slloss_tma<Cc><<<nsm, 1024, smem>>>(logits, targets, sim, out, B);
    } else {
        size_t smem = (size_t)(C * C + ((C + 1) & ~1)) * sizeof(float) + 32 * sizeof(double);
        cudaFuncSetAttribute(slloss_fused_gen, cudaFuncAttributeMaxDynamicSharedMemorySize, (int)smem);
        slloss_fused_gen<<<nsm, 1024, smem>>>(logits, targets, sim, out, B, C);
    }
}

// round 7
// speedup vs baseline: 1.7462x; 1.7462x over previous
#include <cuda_runtime.h>
#include <math.h>

// ---------------------------------------------------------------------------
// SoftLabelLoss: loss = max( (1/B) * sum_i [ e[t_i] - dot(soft[t_i], x_i) + lse(x_i) ], 0 )
//   soft[t][c] = 0.8*(c==t) + 0.2*sim[t][c]/rowsum(sim[t]);  e[t] = sum soft*log(soft)
// Fused single kernel: per-block smem table build -> single pass over logits
// with unroll-4 register pipeline (compile-time C addressing, hoisted
// predicates, split accumulators) -> deterministic fixed-point finalize.
// ---------------------------------------------------------------------------

#define FXSCALE 4294967296.0   // 2^32

__device__ unsigned long long g_sum  = 0ULL;
__device__ unsigned int       g_done = 0u;

// --- warp sum (butterfly shuffle; REDUX.f32 does not exist on sm_103) ----------
__device__ __forceinline__ float warp_sum_f32(float v) {
    #pragma unroll
    for (int o = 16; o; o >>= 1) v += __shfl_xor_sync(0xffffffffu, v, o);
    return v;
}

// --- cooperative in-block table build (any C) -----------------------------------
__device__ __forceinline__ void build_table(const float* __restrict__ sim,
                                            float* s_soft, float* s_ent,
                                            int C, int lane, int warp) {
    for (int t = warp; t < C; t += 32) {
        const float* srow = sim + (size_t)t * C;
        float s = 0.0f;
        for (int c = lane; c < C; c += 32) {
            float v = __ldg(srow + c);
            s_soft[t * C + c] = v;
            s += v;
        }
        s = warp_sum_f32(s);
        float inv = 0.2f / s;                 // smoothing folded in
        float p = 0.0f;
        for (int c = lane; c < C; c += 32) {
            float soft = s_soft[t * C + c] * inv + (c == t ? 0.8f : 0.0f);
            s_soft[t * C + c] = soft;
            p += (soft > 0.0f) ? soft * __logf(soft) : 0.0f;
        }
        p = warp_sum_f32(p);
        if (lane == 0) s_ent[t] = p;
    }
}

// --- deterministic fixed-point finalize -------------------------------------------
__device__ __forceinline__ void block_finalize(float acc, int lane, int warp,
                                               double* s_w, float* out, int B) {
    double d = (double)acc;
    #pragma unroll
    for (int o = 16; o; o >>= 1) d += __shfl_xor_sync(0xffffffffu, d, o);
    if (lane == 0) s_w[warp] = d;
    __syncthreads();
    if (warp == 0) {
        int nw = (blockDim.x + 31) >> 5;
        double v = (lane < nw) ? s_w[lane] : 0.0;
        #pragma unroll
        for (int o = 16; o; o >>= 1) v += __shfl_xor_sync(0xffffffffu, v, o);
        if (lane == 0) {
            long long q = __double2ll_rn(v * FXSCALE);
            atomicAdd(&g_sum, (unsigned long long)q);
            __threadfence();
            unsigned int tk = atomicAdd(&g_done, 1u);
            if (tk == gridDim.x - 1) {
                unsigned long long raw = atomicAdd(&g_sum, 0ULL);
                double loss = ((double)(long long)raw / FXSCALE) / (double)B;
                out[0] = (float)(loss > 0.0 ? loss : 0.0);
                g_sum  = 0ULL;
                g_done = 0u;
                __threadfence();
            }
        }
    }
}

// --- main kernel, compile-time C (C even, 128 < C <= 192) --------------------------
template<int C>
__global__ __launch_bounds__(1024, 1)
void slloss_v6(const float* __restrict__ logits,
               const int*   __restrict__ targets,
               const float* __restrict__ sim,
               float* __restrict__ out, int B) {
    constexpr int C2 = C / 2;                 // 85 for C=170 (float2 per row)
    static_assert((C & 1) == 0 && C2 > 64 && C2 <= 96, "tuned for 128<C<=192");

    extern __shared__ float smemf[];
    float*  s_soft = smemf;                                      // C*C
    float*  s_ent  = smemf + C * C;                              // C
    double* s_w    = (double*)(smemf + C * C + ((C + 1) & ~1));  // 32 doubles

    const int tid  = threadIdx.x;
    const int lane = tid & 31;
    const int warp = tid >> 5;

    build_table(sim, s_soft, s_ent, C, lane, warp);
    __syncthreads();

    const int NW = gridDim.x * 32;
    const int gw = blockIdx.x * 32 + warp;

    long long per = ((long long)B + NW - 1) / NW;
    long long r0  = (long long)gw * per; if (r0 > B) r0 = B;
    long long r1  = r0 + per;            if (r1 > B) r1 = B;

    const bool act2 = lane < (C2 - 64);       // partial third chunk (lane < 21)

    float accD = 0.0f;   // -dot partials (all lanes)
    float accL = 0.0f;   // ent + log(se)  (lane 0 only)

    for (long long base = r0; base < r1; base += 32) {
        const int nrows  = (int)((r1 - base) < 32 ? (r1 - base) : 32);
        const int nrows4 = nrows & ~3;
        int t32 = (lane < nrows) ? __ldg(targets + base + lane) : 0;

        const float2* p = (const float2*)logits + base * C2;

        int r = 0;
        if (nrows4 >= 4) {
            float2 b0[3], b1[3], b2[3], b3[3];
            // prologue: rows 0..3 (constant immediate offsets off p)
            #define LD3(BUF, D)                                       \
                BUF[0] = __ldcs(p + (D) * C2 + lane);                 \
                BUF[1] = __ldcs(p + (D) * C2 + 32 + lane);            \
                if (act2) BUF[2] = __ldcs(p + (D) * C2 + 64 + lane);
            LD3(b0, 0) LD3(b1, 1) LD3(b2, 2) LD3(b3, 3)

            for (; r < nrows4; r += 4) {
                const bool more = (r + 4) < nrows4;

                #define DO_ROW(BUF, D)                                              \
                {                                                                   \
                    int t  = __shfl_sync(0xffffffffu, t32, r + (D));                \
                    int tw = (t >= 0) ? t : 0;                                      \
                    const float2* sw = (const float2*)(s_soft + tw * C);            \
                    float2 x0 = BUF[0], x1 = BUF[1], x2 = BUF[2];                   \
                    if (more) { LD3(BUF, (D) + 4) }                                 \
                    float2 w0 = sw[lane], w1 = sw[lane + 32];                       \
                    float se = __expf(x0.x) + __expf(x0.y)                          \
                             + __expf(x1.x) + __expf(x1.y);                         \
                    float dt = 0.0f;                                                \
                    dt = fmaf(w0.x, x0.x, dt); dt = fmaf(w0.y, x0.y, dt);           \
                    dt = fmaf(w1.x, x1.x, dt); dt = fmaf(w1.y, x1.y, dt);           \
                    if (act2) {                                                     \
                        float2 w2 = sw[lane + 64];                                  \
                        se += __expf(x2.x) + __expf(x2.y);                          \
                        dt = fmaf(w2.x, x2.x, dt); dt = fmaf(w2.y, x2.y, dt);       \
                    }                                                               \
                    se = warp_sum_f32(se);                                          \
                    if (t >= 0) {                                                   \
                        accD -= dt;                                                 \
                        if (lane == 0) accL += s_ent[t] + __logf(se);               \
                    }                                                               \
                }

                DO_ROW(b0, 0)
                DO_ROW(b1, 1)
                DO_ROW(b2, 2)
                DO_ROW(b3, 3)
                #undef DO_ROW

                p += 4 * C2;        // one pointer bump per 4 rows
            }
            #undef LD3
        }

        // scalar tail (<4 rows; rare)
        for (; r < nrows; r++) {
            int t = __shfl_sync(0xffffffffu, t32, r);
            const float* lg = logits + (base + r) * (long long)C;
            const float* sw = s_soft + ((t >= 0) ? t : 0) * C;
            float se = 0.f, dt = 0.f;
            for (int c = lane; c < C; c += 32) {
                float x = __ldg(lg + c);
                se += __expf(x);
                dt = fmaf(sw[c], x, dt);
            }
            se = warp_sum_f32(se);
            if (t >= 0) {
                accD -= dt;
                if (lane == 0) accL += s_ent[t] + __logf(se);
            }
        }
    }

    block_finalize(accD + accL, lane, warp, s_w, out, B);
}

// --- generic fallback (any C) ---------------------------------------------------------
__global__ __launch_bounds__(1024, 1)
void slloss_fused_gen(const float* __restrict__ logits,
                      const int*   __restrict__ targets,
                      const float* __restrict__ sim,
                      float* __restrict__ out,
                      int B, int C) {
    extern __shared__ float smemf[];
    float*  s_soft = smemf;
    float*  s_ent  = smemf + C * C;
    double* s_w    = (double*)(smemf + C * C + ((C + 1) & ~1));

    const int tid = threadIdx.x, lane = tid & 31, warp = tid >> 5;
    build_table(sim, s_soft, s_ent, C, lane, warp);
    __syncthreads();

    const int NW = gridDim.x * 32;
    const int gw = blockIdx.x * 32 + warp;
    long long per = ((long long)B + NW - 1) / NW;
    long long r0 = (long long)gw * per; if (r0 > B) r0 = B;
    long long r1 = r0 + per;            if (r1 > B) r1 = B;

    float acc = 0.0f;
    for (long long row = r0; row < r1; row++) {
        int t = __ldg(&targets[row]);
        if (t < 0) continue;
        const float* lg = logits + (size_t)row * C;
        const float* sw = s_soft + t * C;
        float se = 0.f, dt = 0.f;
        for (int c = lane; c < C; c += 32) {
            float x = __ldg(lg + c);
            se += __expf(x);
            dt = fmaf(sw[c], x, dt);
        }
        se = warp_sum_f32(se);
        acc -= dt;
        if (lane == 0) acc += s_ent[t] + __logf(se);
    }
    block_finalize(acc, lane, warp, s_w, out, B);
}

extern "C" void kernel_launch(void* const* d_in, const int* in_sizes, int n_in,
                              void* d_out, int out_size) {
    const float* logits  = (const float*)d_in[0];
    const int*   targets = (const int*)  d_in[1];
    const float* sim     = (const float*)d_in[2];
    float*       out     = (float*)d_out;

    int B = in_sizes[1];
    int C = in_sizes[0] / B;

    int nsm = 148;
    cudaDeviceGetAttribute(&nsm, cudaDevAttrMultiProcessorCount, 0);

    size_t smem = (size_t)(C * C + ((C + 1) & ~1)) * sizeof(float) + 32 * sizeof(double);

    if (C == 170) {
        cudaFuncSetAttribute(slloss_v6<170>, cudaFuncAttributeMaxDynamicSharedMemorySize, (int)smem);
        slloss_v6<170><<<nsm, 1024, smem>>>(logits, targets, sim, out, B);
    } else {
        cudaFuncSetAttribute(slloss_fused_gen, cudaFuncAttributeMaxDynamicSharedMemorySize, (int)smem);
        slloss_fused_gen<<<nsm, 1024, smem>>>(logits, targets, sim, out, B, C);
    }
}